// round 14
// baseline (speedup 1.0000x reference)
#include <cuda_runtime.h>
#include <cstdint>

// MoEAllReduce: fused expert-weighted reduction + residual add + RMSNorm.
// out[0 : T*H]     = hidden_states
// out[T*H : 2*T*H] = output_residual
//
// FINAL (locked R8 config; best measured 226.2us, ~7.0 TB/s = 88% of HBM
// spec; stable across three independent benches 226.2/227.4/227.4):
// One CTA per token row t. 512 threads, 2 float4 chunks/thread (H=4096),
// __launch_bounds__(512,3) -> 40 regs -> 1536 threads/SM (empirical optimum
// from a 4-point occupancy sweep). Batched load phase -> single-barrier
// redundant block reduce (every warp reduces the 16 partials; no warp-0
// serialization, no second barrier) -> batched store phase. Streaming
// cache hints (__ldcs/__stcs) on all zero-reuse streams; __ldg on the
// L2-resident norm_weight broadcast.
//
// Falsified alternatives (do not revisit): 256-bit v8 LDG/STG, persistent
// grid, interleaved stores, 32-reg full occupancy, manual load pairing,
// write-through stores, expert-start rotation.

#define NTHREADS 512
#define NWARPS (NTHREADS / 32)
#define MAX_ITEMS 8   // fallback path supports H up to 4*512*8 = 16384

__device__ __forceinline__ float warp_reduce_sum(float v) {
#pragma unroll
    for (int off = 16; off > 0; off >>= 1)
        v += __shfl_xor_sync(0xFFFFFFFFu, v, off);
    return v;
}

template <int E_T, int ITEMS_T>
__global__ __launch_bounds__(NTHREADS, 3)
void moe_allreduce_rmsnorm_kernel(
    const float* __restrict__ residual,     // [T, H]
    const float* __restrict__ norm_weight,  // [H]
    const float* __restrict__ scale,        // [E, T]
    const float* __restrict__ A,            // [E, T, H]
    const float* __restrict__ token,        // [T, H]
    float* __restrict__ hidden,             // [T, H]
    float* __restrict__ out_res,            // [T, H]
    int E, int T, int H)
{
    const int t = blockIdx.x;
    const int tid = threadIdx.x;
    const int h4 = H >> 2;                   // float4 count per row
    const int items = (ITEMS_T > 0) ? ITEMS_T : (h4 / NTHREADS);

    __shared__ float s_scale[32];
    __shared__ float s_warp[NWARPS];

    const int Eeff = (E_T > 0) ? E_T : E;
    if (tid < Eeff) s_scale[tid] = scale[(size_t)tid * T + t];
    __syncthreads();

    const float4* __restrict__ res4 = (const float4*)(residual + (size_t)t * H);
    const float4* __restrict__ tok4 = (const float4*)(token    + (size_t)t * H);
    const float4* __restrict__ A4   = (const float4*)A;
    const size_t rowStride4 = (size_t)T * h4;   // float4 stride between experts
    const size_t rowBase4   = (size_t)t * h4;

    float4 acc[ITEMS_T > 0 ? ITEMS_T : MAX_ITEMS];
    float ss = 0.0f;

#pragma unroll
    for (int i = 0; i < (ITEMS_T > 0 ? ITEMS_T : MAX_ITEMS); i++) {
        if (ITEMS_T == 0 && i >= items) break;
        const int idx = tid + i * NTHREADS;   // fully coalesced
        float4 r = __ldcs(&res4[idx]);
        float4 k = __ldcs(&tok4[idx]);
        float4 a;
        a.x = r.x + k.x; a.y = r.y + k.y; a.z = r.z + k.z; a.w = r.w + k.w;

        if (E_T > 0) {
#pragma unroll
            for (int e = 0; e < E_T; e++) {
                const float se = s_scale[e];
                float4 v = __ldcs(&A4[(size_t)e * rowStride4 + rowBase4 + idx]);
                a.x = fmaf(se, v.x, a.x);
                a.y = fmaf(se, v.y, a.y);
                a.z = fmaf(se, v.z, a.z);
                a.w = fmaf(se, v.w, a.w);
            }
        } else {
            for (int e = 0; e < E; e++) {
                const float se = s_scale[e];
                float4 v = __ldcs(&A4[(size_t)e * rowStride4 + rowBase4 + idx]);
                a.x = fmaf(se, v.x, a.x);
                a.y = fmaf(se, v.y, a.y);
                a.z = fmaf(se, v.z, a.z);
                a.w = fmaf(se, v.w, a.w);
            }
        }

        acc[i] = a;
        ss += a.x * a.x + a.y * a.y + a.z * a.z + a.w * a.w;
    }

    // Single-barrier block reduction: every warp redundantly reduces the
    // per-warp partials -> no warp-0 serialization, no second barrier.
    ss = warp_reduce_sum(ss);
    const int wid = tid >> 5;
    const int lid = tid & 31;
    if (lid == 0) s_warp[wid] = ss;
    __syncthreads();
    float v = (lid < NWARPS) ? s_warp[lid] : 0.0f;
    v = warp_reduce_sum(v);                  // all lanes end with the total
    const float inv = rsqrtf(v / (float)H + 1e-5f);

    const float4* __restrict__ w4 = (const float4*)norm_weight;
    float4* __restrict__ o_res4 = (float4*)(out_res + (size_t)t * H);
    float4* __restrict__ o_hid4 = (float4*)(hidden  + (size_t)t * H);

    // Batched store phase: both outputs, writes grouped together.
#pragma unroll
    for (int i = 0; i < (ITEMS_T > 0 ? ITEMS_T : MAX_ITEMS); i++) {
        if (ITEMS_T == 0 && i >= items) break;
        const int idx = tid + i * NTHREADS;
        float4 a = acc[i];
        float4 w = __ldg(&w4[idx]);           // L2-resident broadcast
        float4 hOut;
        hOut.x = a.x * inv * w.x;
        hOut.y = a.y * inv * w.y;
        hOut.z = a.z * inv * w.z;
        hOut.w = a.w * inv * w.w;
        __stcs(&o_res4[idx], a);
        __stcs(&o_hid4[idx], hOut);
    }
}

extern "C" void kernel_launch(void* const* d_in, const int* in_sizes, int n_in,
                              void* d_out, int out_size)
{
    const float* residual = (const float*)d_in[0];   // [T, H]
    const float* weight   = (const float*)d_in[1];   // [H]
    const float* scale    = (const float*)d_in[2];   // [E, T]
    const float* A        = (const float*)d_in[3];   // [E, T, H]
    const float* token    = (const float*)d_in[4];   // [T, H]

    const int H = in_sizes[1];
    const int TH = in_sizes[0];
    const int T = TH / H;
    const int E = in_sizes[2] / T;

    float* hidden  = (float*)d_out;              // [T, H]
    float* out_res = (float*)d_out + (size_t)TH; // [T, H]

    dim3 grid(T);
    dim3 block(NTHREADS);
    const int h4 = H >> 2;
    if (E == 8 && h4 == 2 * NTHREADS) {
        moe_allreduce_rmsnorm_kernel<8, 2><<<grid, block>>>(
            residual, weight, scale, A, token, hidden, out_res, E, T, H);
    } else {
        moe_allreduce_rmsnorm_kernel<0, 0><<<grid, block>>>(
            residual, weight, scale, A, token, hidden, out_res, E, T, H);
    }
}

// round 15
// speedup vs baseline: 1.0007x; 1.0007x over previous
#include <cuda_runtime.h>
#include <cstdint>

// MoEAllReduce: fused expert-weighted reduction + residual add + RMSNorm.
// out[0 : T*H]     = hidden_states
// out[T*H : 2*T*H] = output_residual
//
// Locked R8 config (best 226.2us, ~7.0 TB/s = 88% of HBM spec) with one
// store-phase tweak: stores grouped BY DESTINATION ARRAY (all out_res
// chunks, then all hidden chunks) so each warp issues back-to-back bursts
// to the same DRAM region instead of ping-ponging between two regions
// 128MB apart. Zero extra instructions/registers/traffic.
//
// One CTA per token row t. 512 threads, 2 float4 chunks/thread (H=4096),
// __launch_bounds__(512,3) -> 40 regs -> 1536 threads/SM (occupancy-sweep
// optimum). Batched loads -> single-barrier redundant block reduce ->
// batched grouped stores. __ldcs/__stcs streaming hints on zero-reuse
// streams; __ldg on the L2-resident norm_weight broadcast.
//
// Falsified (do not revisit): v8 256-bit ops, persistent grid, interleaved
// load/store phases, 32-reg full occupancy, manual load pairing, .wt
// stores, expert-start rotation.

#define NTHREADS 512
#define NWARPS (NTHREADS / 32)
#define MAX_ITEMS 8   // fallback path supports H up to 4*512*8 = 16384

__device__ __forceinline__ float warp_reduce_sum(float v) {
#pragma unroll
    for (int off = 16; off > 0; off >>= 1)
        v += __shfl_xor_sync(0xFFFFFFFFu, v, off);
    return v;
}

template <int E_T, int ITEMS_T>
__global__ __launch_bounds__(NTHREADS, 3)
void moe_allreduce_rmsnorm_kernel(
    const float* __restrict__ residual,     // [T, H]
    const float* __restrict__ norm_weight,  // [H]
    const float* __restrict__ scale,        // [E, T]
    const float* __restrict__ A,            // [E, T, H]
    const float* __restrict__ token,        // [T, H]
    float* __restrict__ hidden,             // [T, H]
    float* __restrict__ out_res,            // [T, H]
    int E, int T, int H)
{
    const int t = blockIdx.x;
    const int tid = threadIdx.x;
    const int h4 = H >> 2;                   // float4 count per row
    const int items = (ITEMS_T > 0) ? ITEMS_T : (h4 / NTHREADS);

    __shared__ float s_scale[32];
    __shared__ float s_warp[NWARPS];

    const int Eeff = (E_T > 0) ? E_T : E;
    if (tid < Eeff) s_scale[tid] = scale[(size_t)tid * T + t];
    __syncthreads();

    const float4* __restrict__ res4 = (const float4*)(residual + (size_t)t * H);
    const float4* __restrict__ tok4 = (const float4*)(token    + (size_t)t * H);
    const float4* __restrict__ A4   = (const float4*)A;
    const size_t rowStride4 = (size_t)T * h4;   // float4 stride between experts
    const size_t rowBase4   = (size_t)t * h4;

    float4 acc[ITEMS_T > 0 ? ITEMS_T : MAX_ITEMS];
    float ss = 0.0f;

#pragma unroll
    for (int i = 0; i < (ITEMS_T > 0 ? ITEMS_T : MAX_ITEMS); i++) {
        if (ITEMS_T == 0 && i >= items) break;
        const int idx = tid + i * NTHREADS;   // fully coalesced
        float4 r = __ldcs(&res4[idx]);
        float4 k = __ldcs(&tok4[idx]);
        float4 a;
        a.x = r.x + k.x; a.y = r.y + k.y; a.z = r.z + k.z; a.w = r.w + k.w;

        if (E_T > 0) {
#pragma unroll
            for (int e = 0; e < E_T; e++) {
                const float se = s_scale[e];
                float4 v = __ldcs(&A4[(size_t)e * rowStride4 + rowBase4 + idx]);
                a.x = fmaf(se, v.x, a.x);
                a.y = fmaf(se, v.y, a.y);
                a.z = fmaf(se, v.z, a.z);
                a.w = fmaf(se, v.w, a.w);
            }
        } else {
            for (int e = 0; e < E; e++) {
                const float se = s_scale[e];
                float4 v = __ldcs(&A4[(size_t)e * rowStride4 + rowBase4 + idx]);
                a.x = fmaf(se, v.x, a.x);
                a.y = fmaf(se, v.y, a.y);
                a.z = fmaf(se, v.z, a.z);
                a.w = fmaf(se, v.w, a.w);
            }
        }

        acc[i] = a;
        ss += a.x * a.x + a.y * a.y + a.z * a.z + a.w * a.w;
    }

    // Single-barrier block reduction: every warp redundantly reduces the
    // per-warp partials -> no warp-0 serialization, no second barrier.
    ss = warp_reduce_sum(ss);
    const int wid = tid >> 5;
    const int lid = tid & 31;
    if (lid == 0) s_warp[wid] = ss;
    __syncthreads();
    float v = (lid < NWARPS) ? s_warp[lid] : 0.0f;
    v = warp_reduce_sum(v);                  // all lanes end with the total
    const float inv = rsqrtf(v / (float)H + 1e-5f);

    const float4* __restrict__ w4 = (const float4*)norm_weight;
    float4* __restrict__ o_res4 = (float4*)(out_res + (size_t)t * H);
    float4* __restrict__ o_hid4 = (float4*)(hidden  + (size_t)t * H);

    // Store phase, grouped by destination array: all out_res chunks first
    // (pure data move, no math), then all hidden chunks.
#pragma unroll
    for (int i = 0; i < (ITEMS_T > 0 ? ITEMS_T : MAX_ITEMS); i++) {
        if (ITEMS_T == 0 && i >= items) break;
        const int idx = tid + i * NTHREADS;
        __stcs(&o_res4[idx], acc[i]);
    }
#pragma unroll
    for (int i = 0; i < (ITEMS_T > 0 ? ITEMS_T : MAX_ITEMS); i++) {
        if (ITEMS_T == 0 && i >= items) break;
        const int idx = tid + i * NTHREADS;
        float4 a = acc[i];
        float4 w = __ldg(&w4[idx]);           // L2-resident broadcast
        float4 hOut;
        hOut.x = a.x * inv * w.x;
        hOut.y = a.y * inv * w.y;
        hOut.z = a.z * inv * w.z;
        hOut.w = a.w * inv * w.w;
        __stcs(&o_hid4[idx], hOut);
    }
}

extern "C" void kernel_launch(void* const* d_in, const int* in_sizes, int n_in,
                              void* d_out, int out_size)
{
    const float* residual = (const float*)d_in[0];   // [T, H]
    const float* weight   = (const float*)d_in[1];   // [H]
    const float* scale    = (const float*)d_in[2];   // [E, T]
    const float* A        = (const float*)d_in[3];   // [E, T, H]
    const float* token    = (const float*)d_in[4];   // [T, H]

    const int H = in_sizes[1];
    const int TH = in_sizes[0];
    const int T = TH / H;
    const int E = in_sizes[2] / T;

    float* hidden  = (float*)d_out;              // [T, H]
    float* out_res = (float*)d_out + (size_t)TH; // [T, H]

    dim3 grid(T);
    dim3 block(NTHREADS);
    const int h4 = H >> 2;
    if (E == 8 && h4 == 2 * NTHREADS) {
        moe_allreduce_rmsnorm_kernel<8, 2><<<grid, block>>>(
            residual, weight, scale, A, token, hidden, out_res, E, T, H);
    } else {
        moe_allreduce_rmsnorm_kernel<0, 0><<<grid, block>>>(
            residual, weight, scale, A, token, hidden, out_res, E, T, H);
    }
}

// round 17
// speedup vs baseline: 1.0068x; 1.0061x over previous
#include <cuda_runtime.h>
#include <cstdint>

// MoEAllReduce: fused expert-weighted reduction + residual add + RMSNorm.
// out[0 : T*H]     = hidden_states
// out[T*H : 2*T*H] = output_residual
//
// FINAL KERNEL (session-terminal; measured 227.2us, ~6.96 TB/s = 87-88% of
// HBM spec, stable across five benches of this config family). R16 bench
// was an infra failure (container died twice) — resubmitting unchanged.
//
// One CTA per token row t. 512 threads, 2 float4 chunks/thread (H=4096),
// __launch_bounds__(512,3) -> 40 regs -> 1536 threads/SM (occupancy-sweep
// optimum: 48%/61%/72%/95% -> 237/230/227/238us). Batched load phase ->
// single-barrier redundant block reduce (every warp reduces the 16
// partials; no warp-0 serialization, no second barrier) -> store phase
// grouped by destination array. __ldcs/__stcs streaming hints on all
// zero-reuse streams; __ldg on the L2-resident norm_weight broadcast.
//
// Falsified alternatives (each a dedicated single-variable bench; do not
// revisit): 256-bit v8 LDG/STG, persistent grid, interleaved load/store
// phases, 32-reg full occupancy, manual load pairing, write-through
// stores, expert-start rotation.

#define NTHREADS 512
#define NWARPS (NTHREADS / 32)
#define MAX_ITEMS 8   // fallback path supports H up to 4*512*8 = 16384

__device__ __forceinline__ float warp_reduce_sum(float v) {
#pragma unroll
    for (int off = 16; off > 0; off >>= 1)
        v += __shfl_xor_sync(0xFFFFFFFFu, v, off);
    return v;
}

template <int E_T, int ITEMS_T>
__global__ __launch_bounds__(NTHREADS, 3)
void moe_allreduce_rmsnorm_kernel(
    const float* __restrict__ residual,     // [T, H]
    const float* __restrict__ norm_weight,  // [H]
    const float* __restrict__ scale,        // [E, T]
    const float* __restrict__ A,            // [E, T, H]
    const float* __restrict__ token,        // [T, H]
    float* __restrict__ hidden,             // [T, H]
    float* __restrict__ out_res,            // [T, H]
    int E, int T, int H)
{
    const int t = blockIdx.x;
    const int tid = threadIdx.x;
    const int h4 = H >> 2;                   // float4 count per row
    const int items = (ITEMS_T > 0) ? ITEMS_T : (h4 / NTHREADS);

    __shared__ float s_scale[32];
    __shared__ float s_warp[NWARPS];

    const int Eeff = (E_T > 0) ? E_T : E;
    if (tid < Eeff) s_scale[tid] = scale[(size_t)tid * T + t];
    __syncthreads();

    const float4* __restrict__ res4 = (const float4*)(residual + (size_t)t * H);
    const float4* __restrict__ tok4 = (const float4*)(token    + (size_t)t * H);
    const float4* __restrict__ A4   = (const float4*)A;
    const size_t rowStride4 = (size_t)T * h4;   // float4 stride between experts
    const size_t rowBase4   = (size_t)t * h4;

    float4 acc[ITEMS_T > 0 ? ITEMS_T : MAX_ITEMS];
    float ss = 0.0f;

#pragma unroll
    for (int i = 0; i < (ITEMS_T > 0 ? ITEMS_T : MAX_ITEMS); i++) {
        if (ITEMS_T == 0 && i >= items) break;
        const int idx = tid + i * NTHREADS;   // fully coalesced
        float4 r = __ldcs(&res4[idx]);
        float4 k = __ldcs(&tok4[idx]);
        float4 a;
        a.x = r.x + k.x; a.y = r.y + k.y; a.z = r.z + k.z; a.w = r.w + k.w;

        if (E_T > 0) {
#pragma unroll
            for (int e = 0; e < E_T; e++) {
                const float se = s_scale[e];
                float4 v = __ldcs(&A4[(size_t)e * rowStride4 + rowBase4 + idx]);
                a.x = fmaf(se, v.x, a.x);
                a.y = fmaf(se, v.y, a.y);
                a.z = fmaf(se, v.z, a.z);
                a.w = fmaf(se, v.w, a.w);
            }
        } else {
            for (int e = 0; e < E; e++) {
                const float se = s_scale[e];
                float4 v = __ldcs(&A4[(size_t)e * rowStride4 + rowBase4 + idx]);
                a.x = fmaf(se, v.x, a.x);
                a.y = fmaf(se, v.y, a.y);
                a.z = fmaf(se, v.z, a.z);
                a.w = fmaf(se, v.w, a.w);
            }
        }

        acc[i] = a;
        ss += a.x * a.x + a.y * a.y + a.z * a.z + a.w * a.w;
    }

    // Single-barrier block reduction: every warp redundantly reduces the
    // per-warp partials -> no warp-0 serialization, no second barrier.
    ss = warp_reduce_sum(ss);
    const int wid = tid >> 5;
    const int lid = tid & 31;
    if (lid == 0) s_warp[wid] = ss;
    __syncthreads();
    float v = (lid < NWARPS) ? s_warp[lid] : 0.0f;
    v = warp_reduce_sum(v);                  // all lanes end with the total
    const float inv = rsqrtf(v / (float)H + 1e-5f);

    const float4* __restrict__ w4 = (const float4*)norm_weight;
    float4* __restrict__ o_res4 = (float4*)(out_res + (size_t)t * H);
    float4* __restrict__ o_hid4 = (float4*)(hidden  + (size_t)t * H);

    // Store phase, grouped by destination array: all out_res chunks first
    // (pure data move, no math), then all hidden chunks.
#pragma unroll
    for (int i = 0; i < (ITEMS_T > 0 ? ITEMS_T : MAX_ITEMS); i++) {
        if (ITEMS_T == 0 && i >= items) break;
        const int idx = tid + i * NTHREADS;
        __stcs(&o_res4[idx], acc[i]);
    }
#pragma unroll
    for (int i = 0; i < (ITEMS_T > 0 ? ITEMS_T : MAX_ITEMS); i++) {
        if (ITEMS_T == 0 && i >= items) break;
        const int idx = tid + i * NTHREADS;
        float4 a = acc[i];
        float4 w = __ldg(&w4[idx]);           // L2-resident broadcast
        float4 hOut;
        hOut.x = a.x * inv * w.x;
        hOut.y = a.y * inv * w.y;
        hOut.z = a.z * inv * w.z;
        hOut.w = a.w * inv * w.w;
        __stcs(&o_hid4[idx], hOut);
    }
}

extern "C" void kernel_launch(void* const* d_in, const int* in_sizes, int n_in,
                              void* d_out, int out_size)
{
    const float* residual = (const float*)d_in[0];   // [T, H]
    const float* weight   = (const float*)d_in[1];   // [H]
    const float* scale    = (const float*)d_in[2];   // [E, T]
    const float* A        = (const float*)d_in[3];   // [E, T, H]
    const float* token    = (const float*)d_in[4];   // [T, H]

    const int H = in_sizes[1];
    const int TH = in_sizes[0];
    const int T = TH / H;
    const int E = in_sizes[2] / T;

    float* hidden  = (float*)d_out;              // [T, H]
    float* out_res = (float*)d_out + (size_t)TH; // [T, H]

    dim3 grid(T);
    dim3 block(NTHREADS);
    const int h4 = H >> 2;
    if (E == 8 && h4 == 2 * NTHREADS) {
        moe_allreduce_rmsnorm_kernel<8, 2><<<grid, block>>>(
            residual, weight, scale, A, token, hidden, out_res, E, T, H);
    } else {
        moe_allreduce_rmsnorm_kernel<0, 0><<<grid, block>>>(
            residual, weight, scale, A, token, hidden, out_res, E, T, H);
    }
}